// round 7
// baseline (speedup 1.0000x reference)
#include <cuda_runtime.h>
#include <cuda_bf16.h>
#include <math.h>
#include <stdint.h>

// Problem constants
#define NB    128
#define TSTEPS 32
#define TCAP   33
#define DIM   400
#define HID  1024
#define EMB   512
#define K2   2048      // 2*HID
#define Z4   4096
#define VOC 10000
#define LPOS   16
#define NROWS (TSTEPS * NB)     // 4096
#define VOCP  10112             // 79 * 128
#define SA 40                   // padded smem stride (bf16): conflict-free ldmatrix

// ---------------- device scratch ----------------
__device__ float g_A[NB * LPOS * HID];
__device__ float g_hin[NB * 2 * HID];              // fp32 h0 (only init)
__device__ __nv_bfloat16 g_hinb[NB * K2];          // bf16 [h | attn]
__device__ float g_c[NB * HID];
__device__ float g_xWx[TSTEPS * NB * Z4];
__device__ float g_z[NB * Z4];
__device__ __nv_bfloat16 g_hnb[NROWS * HID];       // bf16 h history
__device__ __nv_bfloat16 g_wvb[VOCP * HID];        // bf16 W_vocab^T [v][k]
__device__ __nv_bfloat16 g_wtb[Z4 * K2];           // bf16 [Wh;Wattn]^T [j][k]
__device__ __nv_bfloat16 g_web[VOC * EMB];         // bf16 W_embed
__device__ __nv_bfloat16 g_wxt[Z4 * EMB];          // bf16 Wx^T [j][k]
__device__ float g_scores[(size_t)NROWS * VOCP];

// ---------------- helpers ----------------
__device__ __forceinline__ uint32_t smem_u32(const void* p) {
    uint32_t a;
    asm("{ .reg .u64 t; cvta.to.shared.u64 t, %1; cvt.u32.u64 %0, t; }" : "=r"(a) : "l"(p));
    return a;
}
__device__ __forceinline__ void ldsm4(uint32_t* r, uint32_t a) {
    asm volatile("ldmatrix.sync.aligned.m8n8.x4.shared.b16 {%0,%1,%2,%3}, [%4];"
        : "=r"(r[0]), "=r"(r[1]), "=r"(r[2]), "=r"(r[3]) : "r"(a));
}
__device__ __forceinline__ void mmabf16(float* d, const uint32_t* a, const uint32_t* b) {
    asm volatile("mma.sync.aligned.m16n8k16.row.col.f32.bf16.bf16.f32 "
        "{%0,%1,%2,%3}, {%4,%5,%6,%7}, {%8,%9}, {%0,%1,%2,%3};"
        : "+f"(d[0]), "+f"(d[1]), "+f"(d[2]), "+f"(d[3])
        : "r"(a[0]), "r"(a[1]), "r"(a[2]), "r"(a[3]), "r"(b[0]), "r"(b[1]));
}
__device__ __forceinline__ void cp16(uint32_t dst, const void* src) {
    asm volatile("cp.async.cg.shared.global [%0], [%1], 16;" :: "r"(dst), "l"(src));
}
#define CP_COMMIT() asm volatile("cp.async.commit_group;" ::: "memory")
#define CP_WAIT1()  asm volatile("cp.async.wait_group 1;" ::: "memory")
#define CP_WAIT0()  asm volatile("cp.async.wait_group 0;" ::: "memory")

// ---------------- zero out ----------------
__global__ void zero_out_k(float* o) { if (threadIdx.x == 0) o[0] = 0.0f; }

// ---------------- A projection + h0 ----------------
__global__ void compute_A_k(const float* __restrict__ features,
                            const float* __restrict__ W_proj,
                            const float* __restrict__ b_proj) {
    __shared__ float fsh[DIM * LPOS];
    const int n = blockIdx.y, tid = threadIdx.x;
    const float* fn = features + n * DIM * LPOS;
    for (int i = tid; i < DIM * LPOS; i += 128) fsh[i] = fn[i];
    __syncthreads();
    const int h = blockIdx.x * 128 + tid;
    float acc[LPOS];
#pragma unroll
    for (int l = 0; l < LPOS; l++) acc[l] = 0.0f;
    const float4* f4 = (const float4*)fsh;
    for (int d = 0; d < DIM; d++) {
        const float wp = W_proj[d * HID + h];
        const float4 a = f4[d * 4 + 0], b = f4[d * 4 + 1];
        const float4 c = f4[d * 4 + 2], e = f4[d * 4 + 3];
        float fv[LPOS] = {a.x, a.y, a.z, a.w, b.x, b.y, b.z, b.w,
                          c.x, c.y, c.z, c.w, e.x, e.y, e.z, e.w};
#pragma unroll
        for (int l = 0; l < LPOS; l++) acc[l] += fv[l] * wp;
    }
    const float bias = b_proj[h];
    float s = 0.0f;
#pragma unroll
    for (int l = 0; l < LPOS; l++) {
        const float v = acc[l] + bias;
        g_A[n * (LPOS * HID) + l * HID + h] = v;
        s += v;
    }
    const float h0 = s * (1.0f / 16.0f);
    g_hin[n * (2 * HID) + h] = h0;
    g_hinb[n * K2 + h] = __float2bfloat16(h0);
    g_c[n * HID + h] = h0;
}

// ---------------- conversions ----------------
__global__ void conv_we_k(const float* __restrict__ W_embed) {
    const int i = blockIdx.x * 1024 + threadIdx.x;
    if (i < VOC * EMB) g_web[i] = __float2bfloat16(W_embed[i]);
}
// Wx [EMB][Z4] -> g_wxt [Z4][EMB]
__global__ void conv_wxt_k(const float* __restrict__ Wx) {
    __shared__ float ts[32][33];
    const int tx = threadIdx.x, ty = threadIdx.y;       // (32, 8)
    const int j0 = blockIdx.x * 32, k0 = blockIdx.y * 32;
#pragma unroll
    for (int jj = 0; jj < 4; jj++) {
        const int k = k0 + ty + jj * 8;
        ts[ty + jj * 8][tx] = Wx[k * Z4 + j0 + tx];
    }
    __syncthreads();
#pragma unroll
    for (int jj = 0; jj < 4; jj++) {
        const int jOut = j0 + ty + jj * 8;
        const int kOut = k0 + tx;
        g_wxt[(size_t)jOut * EMB + kOut] = __float2bfloat16(ts[tx][ty + jj * 8]);
    }
}
// [Wh;Wattn] [K2][Z4] -> g_wtb [Z4][K2]
__global__ void conv_wt_k(const float* __restrict__ Wh,
                          const float* __restrict__ Wattn) {
    __shared__ float ts[32][33];
    const int tx = threadIdx.x, ty = threadIdx.y;
    const int j0 = blockIdx.x * 32, k0 = blockIdx.y * 32;
#pragma unroll
    for (int jj = 0; jj < 4; jj++) {
        const int k = k0 + ty + jj * 8;
        ts[ty + jj * 8][tx] = (k < HID) ? Wh[k * Z4 + j0 + tx]
                                        : Wattn[(k - HID) * Z4 + j0 + tx];
    }
    __syncthreads();
#pragma unroll
    for (int jj = 0; jj < 4; jj++) {
        const int jOut = j0 + ty + jj * 8;
        const int kOut = k0 + tx;
        g_wtb[(size_t)jOut * K2 + kOut] = __float2bfloat16(ts[tx][ty + jj * 8]);
    }
}
// W_vocab [HID][VOC] -> g_wvb [VOCP][HID], zero-padded
__global__ void conv_wv_k(const float* __restrict__ W_vocab) {
    __shared__ float ts[32][33];
    const int tx = threadIdx.x, ty = threadIdx.y;
    const int v0 = blockIdx.x * 32, k0 = blockIdx.y * 32;
    const int v = v0 + tx;
#pragma unroll
    for (int j = 0; j < 4; j++) {
        const int k = k0 + ty + j * 8;
        ts[ty + j * 8][tx] = (v < VOC) ? W_vocab[k * VOC + v] : 0.0f;
    }
    __syncthreads();
#pragma unroll
    for (int j = 0; j < 4; j++) {
        const int vOut = v0 + ty + j * 8;
        const int kOut = k0 + tx;
        g_wvb[vOut * HID + kOut] = __float2bfloat16(ts[tx][ty + j * 8]);
    }
}

// ---------------- embed GEMM (tensor core): xWx = W_embed[tok] @ Wx ----------------
// M=4096, N=4096, K=512. Tile 128x128, chunk 32, double-buffered cp.async.
__global__ void __launch_bounds__(256) embed_mma_k(const int* __restrict__ captions) {
    __shared__ __nv_bfloat16 sA[2][128 * SA];
    __shared__ __nv_bfloat16 sB[2][128 * SA];
    __shared__ int sTok[128];
    const int tid = threadIdx.x, lane = tid & 31, wid = tid >> 5;
    const int wm = (wid >> 2) * 64, wn = (wid & 3) * 32;
    const int r0 = blockIdx.y * 128, j0 = blockIdx.x * 128;
    const uint32_t saB[2] = {smem_u32(sA[0]), smem_u32(sA[1])};
    const uint32_t sbB[2] = {smem_u32(sB[0]), smem_u32(sB[1])};

    if (tid < 128) {
        const int r = r0 + tid, t = r >> 7, n = r & 127;
        sTok[tid] = captions[n * TCAP + t];
    }
    __syncthreads();

    float acc[4][4][4];
#pragma unroll
    for (int mi = 0; mi < 4; mi++)
#pragma unroll
        for (int ni = 0; ni < 4; ni++)
#pragma unroll
            for (int q = 0; q < 4; q++) acc[mi][ni][q] = 0.0f;

    const uint32_t aRow = lane & 15, aK = (lane >> 4) * 8;
    const uint32_t bRow = (lane & 7) + ((lane >> 4) << 3), bK = ((lane >> 3) & 1) * 8;

#define EMB_LOAD(buf, kc)                                                     \
    do {                                                                      \
        _Pragma("unroll")                                                     \
        for (int i = 0; i < 2; i++) {                                         \
            const int q = tid + i * 256;                                      \
            const int row = q >> 2, c4 = q & 3;                               \
            cp16(saB[buf] + row * (SA * 2) + c4 * 16,                         \
                 &g_web[(size_t)sTok[row] * EMB + (kc) + c4 * 8]);            \
            cp16(sbB[buf] + row * (SA * 2) + c4 * 16,                         \
                 &g_wxt[(size_t)(j0 + row) * EMB + (kc) + c4 * 8]);           \
        }                                                                     \
    } while (0)

    EMB_LOAD(0, 0); CP_COMMIT();
    for (int ch = 0; ch < 16; ch++) {
        if (ch + 1 < 16) { EMB_LOAD((ch + 1) & 1, (ch + 1) * 32); CP_COMMIT(); CP_WAIT1(); }
        else CP_WAIT0();
        __syncthreads();
        const uint32_t sa = saB[ch & 1], sb = sbB[ch & 1];
#pragma unroll
        for (int ks = 0; ks < 2; ks++) {
            uint32_t a[4][4], b[2][4];
#pragma unroll
            for (int mi = 0; mi < 4; mi++)
                ldsm4(a[mi], sa + ((wm + mi * 16 + aRow) * SA + ks * 16 + aK) * 2);
#pragma unroll
            for (int nh = 0; nh < 2; nh++)
                ldsm4(b[nh], sb + ((wn + nh * 16 + bRow) * SA + ks * 16 + bK) * 2);
#pragma unroll
            for (int mi = 0; mi < 4; mi++)
#pragma unroll
                for (int ni = 0; ni < 4; ni++)
                    mmabf16(acc[mi][ni], a[mi], &b[ni >> 1][(ni & 1) * 2]);
        }
        __syncthreads();
    }
    const int mBase = r0 + wm + (lane >> 2);
    const int nOff = 2 * (lane & 3);
#pragma unroll
    for (int mi = 0; mi < 4; mi++) {
#pragma unroll
        for (int ni = 0; ni < 4; ni++) {
            const int j = j0 + wn + ni * 8 + nOff;
            const int m0 = mBase + mi * 16;
            *(float2*)&g_xWx[(size_t)m0 * Z4 + j] = make_float2(acc[mi][ni][0], acc[mi][ni][1]);
            *(float2*)&g_xWx[(size_t)(m0 + 8) * Z4 + j] = make_float2(acc[mi][ni][2], acc[mi][ni][3]);
        }
    }
}

// ---------------- fused gates(t-1) + attention(t) ----------------
// t in [0, 32]. Phase1 (gates for step t-1) if t>0; Phase2 (attn for step t) if t<32.
__global__ void __launch_bounds__(512) fused_ga_k(int t) {
    __shared__ float hsh[HID];
    __shared__ float e_sh[LPOS];
    __shared__ float w_sh[LPOS];
    const int n = blockIdx.x, tid = threadIdx.x;
    const int warp = tid >> 5, lane = tid & 31;

    if (t > 0) {
        const float* zr = g_z + n * Z4;
        for (int h = tid; h < HID; h += 512) {
            const float ai = zr[h], af = zr[h + HID], ao = zr[h + 2 * HID], ag = zr[h + 3 * HID];
            const float gi = 1.0f / (1.0f + expf(-ai));
            const float gf = 1.0f / (1.0f + expf(-af));
            const float go = 1.0f / (1.0f + expf(-ao));
            const float gg = tanhf(ag);
            const float c = gf * g_c[n * HID + h] + gi * gg;
            const float hh = go * tanhf(c);
            g_c[n * HID + h] = c;
            hsh[h] = hh;
            g_hinb[n * K2 + h] = __float2bfloat16(hh);
            g_hnb[(size_t)(t - 1) * (NB * HID) + n * HID + h] = __float2bfloat16(hh);
        }
    } else {
        for (int h = tid; h < HID; h += 512) hsh[h] = g_hin[n * (2 * HID) + h];
    }
    __syncthreads();

    if (t < TSTEPS) {
        const float* An = g_A + n * (LPOS * HID);
        float s = 0.0f;
        const float* Al = An + warp * HID;
        for (int h = lane; h < HID; h += 32) s += hsh[h] * Al[h];
#pragma unroll
        for (int off = 16; off > 0; off >>= 1) s += __shfl_down_sync(0xFFFFFFFF, s, off);
        if (lane == 0) e_sh[warp] = s * 0.03125f;
        __syncthreads();
        if (tid == 0) {
            float m = -1e30f;
#pragma unroll
            for (int l = 0; l < LPOS; l++) m = fmaxf(m, e_sh[l]);
            float ss = 0.0f;
#pragma unroll
            for (int l = 0; l < LPOS; l++) { float w = expf(e_sh[l] - m); w_sh[l] = w; ss += w; }
            const float inv = 1.0f / ss;
#pragma unroll
            for (int l = 0; l < LPOS; l++) w_sh[l] *= inv;
        }
        __syncthreads();
        for (int h = tid; h < HID; h += 512) {
            float a = 0.0f;
#pragma unroll
            for (int l = 0; l < LPOS; l++) a += An[l * HID + h] * w_sh[l];
            g_hinb[n * K2 + HID + h] = __float2bfloat16(a);
        }
    }
}

// ---------------- step GEMM (tensor core): z = hinb @ wtb^T + xWx + b ----------------
// M=128, N=64/CTA (grid 64), K=2048 chunk 32, double-buffered.
__global__ void __launch_bounds__(256) step_mma_k(const float* __restrict__ bvec, int t) {
    __shared__ __nv_bfloat16 sA[2][128 * SA];
    __shared__ __nv_bfloat16 sB[2][64 * SA];
    const int tid = threadIdx.x, lane = tid & 31, wid = tid >> 5;
    const int wm = (wid >> 2) * 64, wn = (wid & 3) * 16;
    const int j0 = blockIdx.x * 64;
    const uint32_t saB[2] = {smem_u32(sA[0]), smem_u32(sA[1])};
    const uint32_t sbB[2] = {smem_u32(sB[0]), smem_u32(sB[1])};

    float acc[4][2][4];
#pragma unroll
    for (int mi = 0; mi < 4; mi++)
#pragma unroll
        for (int ni = 0; ni < 2; ni++)
#pragma unroll
            for (int q = 0; q < 4; q++) acc[mi][ni][q] = 0.0f;

    const uint32_t aRow = lane & 15, aK = (lane >> 4) * 8;
    const uint32_t bRow = (lane & 7) + ((lane >> 4) << 3), bK = ((lane >> 3) & 1) * 8;

#define STEP_LOAD(buf, kc)                                                    \
    do {                                                                      \
        _Pragma("unroll")                                                     \
        for (int i = 0; i < 2; i++) {                                         \
            const int q = tid + i * 256;                                      \
            const int row = q >> 2, c4 = q & 3;                               \
            cp16(saB[buf] + row * (SA * 2) + c4 * 16,                         \
                 &g_hinb[row * K2 + (kc) + c4 * 8]);                          \
        }                                                                     \
        {                                                                     \
            const int row = tid >> 2, c4 = tid & 3;                           \
            cp16(sbB[buf] + row * (SA * 2) + c4 * 16,                         \
                 &g_wtb[(size_t)(j0 + row) * K2 + (kc) + c4 * 8]);            \
        }                                                                     \
    } while (0)

    STEP_LOAD(0, 0); CP_COMMIT();
    for (int ch = 0; ch < 64; ch++) {
        if (ch + 1 < 64) { STEP_LOAD((ch + 1) & 1, (ch + 1) * 32); CP_COMMIT(); CP_WAIT1(); }
        else CP_WAIT0();
        __syncthreads();
        const uint32_t sa = saB[ch & 1], sb = sbB[ch & 1];
#pragma unroll
        for (int ks = 0; ks < 2; ks++) {
            uint32_t a[4][4], b[4];
#pragma unroll
            for (int mi = 0; mi < 4; mi++)
                ldsm4(a[mi], sa + ((wm + mi * 16 + aRow) * SA + ks * 16 + aK) * 2);
            ldsm4(b, sb + ((wn + bRow) * SA + ks * 16 + bK) * 2);
#pragma unroll
            for (int mi = 0; mi < 4; mi++)
#pragma unroll
                for (int ni = 0; ni < 2; ni++)
                    mmabf16(acc[mi][ni], a[mi], &b[ni * 2]);
        }
        __syncthreads();
    }
    const int mBase = wm + (lane >> 2);
    const int nOff = 2 * (lane & 3);
#pragma unroll
    for (int mi = 0; mi < 4; mi++) {
#pragma unroll
        for (int ni = 0; ni < 2; ni++) {
            const int j = j0 + wn + ni * 8 + nOff;
            const float2 bb = *(const float2*)&bvec[j];
            const int m0 = mBase + mi * 16;
            const float2 x0 = *(const float2*)&g_xWx[(size_t)(t * NB + m0) * Z4 + j];
            const float2 x1 = *(const float2*)&g_xWx[(size_t)(t * NB + m0 + 8) * Z4 + j];
            *(float2*)&g_z[m0 * Z4 + j] =
                make_float2(acc[mi][ni][0] + x0.x + bb.x, acc[mi][ni][1] + x0.y + bb.y);
            *(float2*)&g_z[(m0 + 8) * Z4 + j] =
                make_float2(acc[mi][ni][2] + x1.x + bb.x, acc[mi][ni][3] + x1.y + bb.y);
        }
    }
}

// ---------------- scores GEMM (tensor core): scores = hnb @ wvb^T + b ----------------
// M=128, N=128/CTA, grid (79, 32), K=1024 chunk 32, double-buffered.
__global__ void __launch_bounds__(256) score_gemm_k(const float* __restrict__ b_vocab) {
    __shared__ __nv_bfloat16 sA[2][128 * SA];
    __shared__ __nv_bfloat16 sB[2][128 * SA];
    const int tid = threadIdx.x, lane = tid & 31, wid = tid >> 5;
    const int wm = (wid >> 2) * 64, wn = (wid & 3) * 32;
    const int r0 = blockIdx.y * 128, v0 = blockIdx.x * 128;
    const uint32_t saB[2] = {smem_u32(sA[0]), smem_u32(sA[1])};
    const uint32_t sbB[2] = {smem_u32(sB[0]), smem_u32(sB[1])};

    float acc[4][4][4];
#pragma unroll
    for (int mi = 0; mi < 4; mi++)
#pragma unroll
        for (int ni = 0; ni < 4; ni++)
#pragma unroll
            for (int q = 0; q < 4; q++) acc[mi][ni][q] = 0.0f;

    const uint32_t aRow = lane & 15, aK = (lane >> 4) * 8;
    const uint32_t bRow = (lane & 7) + ((lane >> 4) << 3), bK = ((lane >> 3) & 1) * 8;

#define SC_LOAD(buf, kc)                                                      \
    do {                                                                      \
        _Pragma("unroll")                                                     \
        for (int i = 0; i < 2; i++) {                                         \
            const int q = tid + i * 256;                                      \
            const int row = q >> 2, c4 = q & 3;                               \
            cp16(saB[buf] + row * (SA * 2) + c4 * 16,                         \
                 &g_hnb[(size_t)(r0 + row) * HID + (kc) + c4 * 8]);           \
            cp16(sbB[buf] + row * (SA * 2) + c4 * 16,                         \
                 &g_wvb[(size_t)(v0 + row) * HID + (kc) + c4 * 8]);           \
        }                                                                     \
    } while (0)

    SC_LOAD(0, 0); CP_COMMIT();
    for (int ch = 0; ch < 32; ch++) {
        if (ch + 1 < 32) { SC_LOAD((ch + 1) & 1, (ch + 1) * 32); CP_COMMIT(); CP_WAIT1(); }
        else CP_WAIT0();
        __syncthreads();
        const uint32_t sa = saB[ch & 1], sb = sbB[ch & 1];
#pragma unroll
        for (int ks = 0; ks < 2; ks++) {
            uint32_t a[4][4], b[2][4];
#pragma unroll
            for (int mi = 0; mi < 4; mi++)
                ldsm4(a[mi], sa + ((wm + mi * 16 + aRow) * SA + ks * 16 + aK) * 2);
#pragma unroll
            for (int nh = 0; nh < 2; nh++)
                ldsm4(b[nh], sb + ((wn + nh * 16 + bRow) * SA + ks * 16 + bK) * 2);
#pragma unroll
            for (int mi = 0; mi < 4; mi++)
#pragma unroll
                for (int ni = 0; ni < 4; ni++)
                    mmabf16(acc[mi][ni], a[mi], &b[ni >> 1][(ni & 1) * 2]);
        }
        __syncthreads();
    }
    const int mBase = r0 + wm + (lane >> 2);
    const int nOff = 2 * (lane & 3);
#pragma unroll
    for (int mi = 0; mi < 4; mi++) {
#pragma unroll
        for (int ni = 0; ni < 4; ni++) {
            const int v = v0 + wn + ni * 8 + nOff;
            const float bv0 = (v < VOC) ? b_vocab[v] : 0.0f;
            const float bv1 = (v + 1 < VOC) ? b_vocab[v + 1] : 0.0f;
            const int m0 = mBase + mi * 16;
            *(float2*)&g_scores[(size_t)m0 * VOCP + v] =
                make_float2(acc[mi][ni][0] + bv0, acc[mi][ni][1] + bv1);
            *(float2*)&g_scores[(size_t)(m0 + 8) * VOCP + v] =
                make_float2(acc[mi][ni][2] + bv0, acc[mi][ni][3] + bv1);
        }
    }
}

// ---------------- streaming log-softmax NLL ----------------
__global__ void nll_k(const int* __restrict__ captions, float* __restrict__ out) {
    __shared__ float red[256];
    const int r = blockIdx.x, tid = threadIdx.x;
    const int t = r >> 7, n = r & 127;
    const float* row = g_scores + (size_t)r * VOCP;
    float s = 0.0f;
    for (int v = tid; v < VOC; v += 256) s += __expf(row[v]);
    red[tid] = s;
    __syncthreads();
    for (int st = 128; st > 0; st >>= 1) {
        if (tid < st) red[tid] += red[tid + st];
        __syncthreads();
    }
    if (tid == 0) {
        const int tg = captions[n * TCAP + t + 1];
        if (tg != 0) atomicAdd(out, (logf(red[0]) - row[tg]) * (1.0f / (float)NB));
    }
}

// ---------------- launcher ----------------
extern "C" void kernel_launch(void* const* d_in, const int* in_sizes, int n_in,
                              void* d_out, int out_size) {
    const float* features = (const float*)d_in[0];
    const int*   captions = (const int*)  d_in[1];
    const float* W_embed  = (const float*)d_in[2];
    const float* W_proj   = (const float*)d_in[3];
    const float* b_proj   = (const float*)d_in[4];
    const float* Wx       = (const float*)d_in[5];
    const float* Wh       = (const float*)d_in[6];
    const float* Wattn    = (const float*)d_in[7];
    const float* bvec     = (const float*)d_in[8];
    const float* W_vocab  = (const float*)d_in[9];
    const float* b_vocab  = (const float*)d_in[10];
    float* out = (float*)d_out;

    zero_out_k<<<1, 32>>>(out);
    compute_A_k<<<dim3(8, NB), 128>>>(features, W_proj, b_proj);
    conv_we_k<<<(VOC * EMB + 1023) / 1024, 1024>>>(W_embed);
    conv_wxt_k<<<dim3(Z4 / 32, EMB / 32), dim3(32, 8)>>>(Wx);
    conv_wt_k<<<dim3(Z4 / 32, K2 / 32), dim3(32, 8)>>>(Wh, Wattn);
    conv_wv_k<<<dim3(VOCP / 32, HID / 32), dim3(32, 8)>>>(W_vocab);
    embed_mma_k<<<dim3(Z4 / 128, NROWS / 128), 256>>>(captions);
    for (int t = 0; t < TSTEPS; t++) {
        fused_ga_k<<<NB, 512>>>(t);
        step_mma_k<<<64, 256>>>(bvec, t);
    }
    fused_ga_k<<<NB, 512>>>(TSTEPS);   // final gates for t=31
    score_gemm_k<<<dim3(VOCP / 128, NROWS / 128), 256>>>(b_vocab);
    nll_k<<<NROWS, 256>>>(captions, out);
}